// round 14
// baseline (speedup 1.0000x reference)
#include <cuda_runtime.h>
#include <cuda_fp16.h>
#include <cstdint>

typedef unsigned long long u64;

__device__ __forceinline__ uint32_t smem_u32(const void* p) {
    uint32_t a;
    asm("{ .reg .u64 t; cvta.to.shared.u64 t, %1; cvt.u32.u64 %0, t; }" : "=r"(a) : "l"(p));
    return a;
}
__device__ __forceinline__ void ldsm4(uint32_t* r, uint32_t addr) {
    asm volatile("ldmatrix.sync.aligned.m8n8.x4.shared.b16 {%0,%1,%2,%3}, [%4];"
                 : "=r"(r[0]), "=r"(r[1]), "=r"(r[2]), "=r"(r[3]) : "r"(addr));
}
__device__ __forceinline__ void mma16816(float* d, const uint32_t* a, const uint32_t* b) {
    asm volatile(
        "mma.sync.aligned.m16n8k16.row.col.f32.f16.f16.f32 "
        "{%0,%1,%2,%3}, {%4,%5,%6,%7}, {%8,%9}, {%0,%1,%2,%3};"
        : "+f"(d[0]), "+f"(d[1]), "+f"(d[2]), "+f"(d[3])
        : "r"(a[0]), "r"(a[1]), "r"(a[2]), "r"(a[3]), "r"(b[0]), "r"(b[1]));
}
__device__ __forceinline__ void cpasync16(uint32_t dst, const void* src) {
    asm volatile("cp.async.cg.shared.global [%0], [%1], 16;" :: "r"(dst), "l"(src));
}
#define CP_COMMIT() asm volatile("cp.async.commit_group;" ::: "memory")
#define CP_WAIT1()  asm volatile("cp.async.wait_group 1;" ::: "memory")
#define CP_WAIT0()  asm volatile("cp.async.wait_group 0;" ::: "memory")

// pack 2 floats -> half2 bits (lo in low half)
__device__ __forceinline__ uint32_t packh(float lo, float hi) {
    __half2 h = __floats2half2_rn(lo, hi);
    return *reinterpret_cast<uint32_t*>(&h);
}

// ---------------- problem constants ----------------
constexpr int Bb = 4, Tt = 2048, Cc = 1024, Hh = 16, HD = 64;
constexpr int BT = Bb * Tt;
constexpr int Kd = 1024;
// GEMM: single-term fp16, BK=64, 2 tiles (A, B) x 16KB; double buffer = 64KB, 2 CTAs/SM
constexpr int GTILE = 16384;
constexpr int STAGE = 2 * GTILE;       // 32768
constexpr int GSM_BYTES = 2 * STAGE;   // 65536
constexpr int ASTAGE = 32768;          // attn: Kh (16KB) + Vth (16KB)
constexpr int ASM_BYTES = 2 * ASTAGE;  // 64KB -> 2 CTAs/SM

// ---------------- scratch (device globals) ----------------
constexpr size_t QKV = (size_t)Bb * Hh * Tt * HD;   // 8388608
__device__ __half g_qh[QKV];                        // [b,h,t,d], pre-scaled 0.125
__device__ __half g_kh[QKV];                        // [b,h,t,d]
__device__ __half g_vth[QKV];                       // [b,h,d,t] (transposed)
__device__ __half gx_h[(size_t)BT * Kd];            // x single fp16
__device__ __half gy_h[(size_t)BT * Kd];            // y single fp16
__device__ __half gwa_h[(size_t)3072 * Kd];
__device__ __half gwp_h[(size_t)1024 * Kd];

// ---------------- conversion kernels ----------------
__global__ void k_half(const float4* __restrict__ src, __half2* __restrict__ h, int n4)
{
    int i = blockIdx.x * blockDim.x + threadIdx.x;
    if (i >= n4) return;
    float4 v = src[i];
    h[i * 2]     = __floats2half2_rn(v.x, v.y);
    h[i * 2 + 1] = __floats2half2_rn(v.z, v.w);
}

__global__ void k_splitT(const float* __restrict__ src, __half* __restrict__ h, int Ncols)
{
    __shared__ float ts[32][33];
    int tx = threadIdx.x, ty = threadIdx.y;
    int c0 = blockIdx.x * 32, r0 = blockIdx.y * 32;
#pragma unroll
    for (int i = 0; i < 4; i++)
        ts[ty + i * 8][tx] = src[(size_t)(r0 + ty + i * 8) * Ncols + c0 + tx];
    __syncthreads();
#pragma unroll
    for (int i = 0; i < 4; i++) {
        int n = c0 + ty + i * 8, k = r0 + tx;
        h[(size_t)n * 1024 + k] = __float2half_rn(ts[tx][ty + i * 8]);
    }
}

// ---------------------------------------------------------------------------
// fp16 single-term GEMM: D = A*B^T. BK=64, 128B-pitch, 0x70 swizzle,
// cp.async double-buffered, 2 CTAs/SM (round-8 verified config).
// MODE 0: q (scaled) and k single fp16 [b,h,t,d]; V^T single via smem transpose.
// MODE 1: fp32 out + bias.
// ---------------------------------------------------------------------------
template <int MODE>
__global__ __launch_bounds__(256, 2) void sa_gemm_mma(
    const __half* __restrict__ A, const __half* __restrict__ B,
    const float* __restrict__ bias, float* __restrict__ out, int N)
{
    extern __shared__ char smem[];
    uint32_t sb = smem_u32(smem);
    int tid = threadIdx.x, lane = tid & 31, warp = tid >> 5;
    int m0 = blockIdx.y * 128, n0 = blockIdx.x * 128;
    int wm = (warp >> 2) * 64, wn = (warp & 3) * 32;

    auto load_stage = [&](int st, int c) {
        uint32_t sbase = sb + st * STAGE;
        int kc0 = c * 64;
#pragma unroll
        for (int i = 0; i < 8; i++) {
            int id = tid + i * 256;            // 2048 16B chunks
            int tile = id >> 10, rem = id & 1023;
            int row = rem >> 3, cch = rem & 7;
            const __half* src = (tile ? B : A) + (size_t)((tile ? n0 : m0) + row) * Kd + kc0 + cch * 8;
            uint32_t off = row * 128 + cch * 16;
            off ^= ((off >> 3) & 0x70);
            cpasync16(sbase + tile * GTILE + off, src);
        }
    };

    float acc[4][4][4];
#pragma unroll
    for (int a = 0; a < 4; a++)
#pragma unroll
        for (int b = 0; b < 4; b++)
#pragma unroll
            for (int e = 0; e < 4; e++) acc[a][b][e] = 0.0f;

    load_stage(0, 0);
    CP_COMMIT();

    for (int c = 0; c < 16; c++) {
        if (c + 1 < 16) load_stage((c + 1) & 1, c + 1);
        CP_COMMIT();
        CP_WAIT1();
        __syncthreads();
        uint32_t sbase = sb + (c & 1) * STAGE;
#pragma unroll
        for (int ks = 0; ks < 4; ks++) {
            uint32_t ah[4][4], bhf[4][2];
#pragma unroll
            for (int mt = 0; mt < 4; mt++) {
                int row = wm + mt * 16 + (lane & 15);
                int cch = ks * 2 + (lane >> 4);
                uint32_t off = row * 128 + cch * 16;
                off ^= ((off >> 3) & 0x70);
                ldsm4(ah[mt], sbase + off);
            }
#pragma unroll
            for (int nt = 0; nt < 2; nt++) {
                int row = wn + nt * 16 + (lane & 15);
                int cch = ks * 2 + (lane >> 4);
                uint32_t off = row * 128 + cch * 16;
                off ^= ((off >> 3) & 0x70);
                uint32_t t[4];
                ldsm4(t, sbase + GTILE + off);
                bhf[nt * 2][0] = t[0]; bhf[nt * 2][1] = t[2];
                bhf[nt * 2 + 1][0] = t[1]; bhf[nt * 2 + 1][1] = t[3];
            }
#pragma unroll
            for (int mt = 0; mt < 4; mt++)
#pragma unroll
                for (int j = 0; j < 4; j++)
                    mma16816(acc[mt][j], ah[mt], bhf[j]);
        }
        __syncthreads();
    }

    if (MODE == 0 && n0 >= 2048) {
        // ---- V CTA: smem-staged transpose -> coalesced [b,h,d,t] stores ----
        constexpr int PITCH = 136;
        __half* svh = reinterpret_cast<__half*>(smem);
        int bidx = m0 >> 11, tbase = m0 & 2047;
#pragma unroll
        for (int hl = 0; hl < 2; hl++) {
            if (hl) __syncthreads();
#pragma unroll
            for (int mt = 0; mt < 4; mt++)
#pragma unroll
                for (int j = 0; j < 4; j++) {
                    int n = n0 + wn + j * 8 + (lane & 3) * 2;
                    if (((n >> 6) & 1) != hl) continue;
                    int dd = n & 63;
#pragma unroll
                    for (int half = 0; half < 2; half++) {
                        int tl = wm + mt * 16 + (lane >> 2) + half * 8;
                        svh[dd * PITCH + tl]       = __float2half_rn(acc[mt][j][half * 2]);
                        svh[(dd + 1) * PITCH + tl] = __float2half_rn(acc[mt][j][half * 2 + 1]);
                    }
                }
            __syncthreads();
            int h = ((n0 & 1023) >> 6) + hl;
            int bhn = bidx * 16 + h;
#pragma unroll
            for (int i = 0; i < 4; i++) {
                int id = tid + i * 256;          // 1024: 64 dd x 16 tc
                int dd = id >> 4, tc = id & 15;
                uint4 v = *reinterpret_cast<const uint4*>(svh + dd * PITCH + tc * 8);
                *reinterpret_cast<uint4*>(g_vth +
                    (((size_t)bhn * HD + dd) * Tt + tbase + tc * 8)) = v;
            }
        }
        return;
    }

#pragma unroll
    for (int mt = 0; mt < 4; mt++)
#pragma unroll
        for (int j = 0; j < 4; j++) {
            int n = n0 + wn + j * 8 + (lane & 3) * 2;
            int mA = m0 + wm + mt * 16 + (lane >> 2);
#pragma unroll
            for (int half = 0; half < 2; half++) {
                int m = mA + half * 8;
                float f0 = acc[mt][j][half * 2], f1 = acc[mt][j][half * 2 + 1];
                if (MODE == 0) {
                    int part = n >> 10, c1 = n & 1023, h = c1 >> 6, dd = c1 & 63;
                    int bidx = m >> 11, t = m & 2047;
                    int bhn = bidx * 16 + h;
                    size_t idx = ((size_t)bhn * Tt + t) * HD + dd;
                    if (part == 0) {
                        *reinterpret_cast<uint32_t*>(g_qh + idx) =
                            packh(f0 * 0.125f, f1 * 0.125f);
                    } else {
                        *reinterpret_cast<uint32_t*>(g_kh + idx) = packh(f0, f1);
                    }
                } else {
                    f0 += __ldg(bias + n);
                    f1 += __ldg(bias + n + 1);
                    float2 v = {f0, f1};
                    *reinterpret_cast<float2*>(out + (size_t)m * N + n) = v;
                }
            }
        }
}

// ---------------------------------------------------------------------------
// Pure-fp16 flash attention, 2 CTAs/SM. Each 128-key tile processed in two
// 64-column halves (s[8][4] accumulator -> fits 128 regs). Online softmax
// updated per half (exact composition). S and PV single-term fp16 mma.
// ---------------------------------------------------------------------------
__global__ __launch_bounds__(256, 2) void sa_attn_mma(const int* __restrict__ pad)
{
    extern __shared__ char smem[];
    __shared__ float pm[2][128];
    uint32_t sb = smem_u32(smem);
    int tid = threadIdx.x, lane = tid & 31, warp = tid >> 5;
    int qt = (int)gridDim.x - 1 - (int)blockIdx.x;   // big tiles first
    int bh = blockIdx.y, bb = bh >> 4, hh = bh & 15;
    int q0 = qt * 128;
    size_t kbase = (size_t)bh * Tt * HD;
    size_t vbase = (size_t)bh * HD * Tt;

    // ---- stage Q (single fp16), extract fragments ----
#pragma unroll
    for (int i = 0; i < 4; i++) {
        int id = tid + i * 256;            // 1024: 128 rows x 8 chunks
        int row = id >> 3, c = id & 7;
        const __half* src = g_qh + kbase + (size_t)(q0 + row) * HD + c * 8;
        cpasync16(sb + row * 128 + ((c ^ (row & 7)) << 4), src);
    }
    CP_COMMIT();
    CP_WAIT0();
    __syncthreads();
    uint32_t qh[4][4];
#pragma unroll
    for (int ks = 0; ks < 4; ks++) {
        int row = warp * 16 + (lane & 15), cch = ks * 2 + (lane >> 4);
        uint32_t off = row * 128 + ((cch ^ (row & 7)) << 4);
        ldsm4(qh[ks], sb + off);
    }
    __syncthreads();

    auto load_stage = [&](int st, int kt) {
        uint32_t sbase = sb + st * ASTAGE;
        int k0 = kt * 128;
#pragma unroll
        for (int i = 0; i < 8; i++) {
            int id = tid + i * 256;
            int part = id >> 10, rem = id & 1023;
            if (part == 0) {
                int row = rem >> 3, c = rem & 7;
                const __half* src = g_kh + kbase + (size_t)(k0 + row) * HD + c * 8;
                cpasync16(sbase + row * 128 + ((c ^ (row & 7)) << 4), src);
            } else {
                int row = rem >> 4, c = rem & 15;
                const __half* src = g_vth + vbase + (size_t)row * Tt + k0 + c * 8;
                cpasync16(sbase + 16384 + row * 256 + ((c ^ (row & 7)) << 4), src);
            }
        }
        if (tid < 128) pm[st][tid] = pad[bb * Tt + k0 + tid] ? 0.0f : -1e30f;
    };

    float o[8][4];
#pragma unroll
    for (int i = 0; i < 8; i++)
#pragma unroll
        for (int e = 0; e < 4; e++) o[i][e] = 0.0f;
    float mrow[2] = {-1e30f, -1e30f}, lrow[2] = {0.0f, 0.0f};

    load_stage(0, 0);
    CP_COMMIT();

    for (int kt = 0; kt <= qt; kt++) {
        CP_WAIT0();
        __syncthreads();                     // all warps done with prev buffer
        if (kt < qt) { load_stage((kt + 1) & 1, kt + 1); CP_COMMIT(); }
        uint32_t sbase = sb + (kt & 1) * ASTAGE;
        int c2 = 2 * (lane & 3);

#pragma unroll
        for (int hf = 0; hf < 2; hf++) {
            // ---- S(half) = Q K^T over 64 key-columns ----
            float s[8][4];
#pragma unroll
            for (int nt = 0; nt < 8; nt++)
#pragma unroll
                for (int e = 0; e < 4; e++) s[nt][e] = 0.0f;

#pragma unroll
            for (int ntp = 0; ntp < 4; ntp++) {
#pragma unroll
                for (int ks = 0; ks < 4; ks++) {
                    int row = hf * 64 + ntp * 16 + (lane & 15);
                    int cch = ks * 2 + (lane >> 4);
                    uint32_t off = row * 128 + ((cch ^ (row & 7)) << 4);
                    uint32_t t[4], kh0[2], kh1[2];
                    ldsm4(t, sbase + off);
                    kh0[0] = t[0]; kh0[1] = t[2]; kh1[0] = t[1]; kh1[1] = t[3];
                    mma16816(s[2 * ntp], qh[ks], kh0);
                    mma16816(s[2 * ntp + 1], qh[ks], kh1);
                }
            }

            // ---- masks ----
#pragma unroll
            for (int nt = 0; nt < 8; nt++) {
                int colb = hf * 64 + nt * 8 + c2;
                float m0v = pm[kt & 1][colb];
                float m1v = pm[kt & 1][colb + 1];
                s[nt][0] += m0v; s[nt][1] += m1v; s[nt][2] += m0v; s[nt][3] += m1v;
            }
            if (kt == qt) {
                int r0 = warp * 16 + (lane >> 2), r1 = r0 + 8;
#pragma unroll
                for (int nt = 0; nt < 8; nt++) {
                    int col0 = hf * 64 + nt * 8 + c2;
                    if (col0 > r0)     s[nt][0] = -1e30f;
                    if (col0 + 1 > r0) s[nt][1] = -1e30f;
                    if (col0 > r1)     s[nt][2] = -1e30f;
                    if (col0 + 1 > r1) s[nt][3] = -1e30f;
                }
            }

            // ---- online softmax update (2 rows per lane) ----
#pragma unroll
            for (int h2 = 0; h2 < 2; h2++) {
                float mt = -1e30f;
#pragma unroll
                for (int nt = 0; nt < 8; nt++)
                    mt = fmaxf(mt, fmaxf(s[nt][2 * h2], s[nt][2 * h2 + 1]));
                mt = fmaxf(mt, __shfl_xor_sync(0xffffffffu, mt, 1));
                mt = fmaxf(mt, __shfl_xor_sync(0xffffffffu, mt, 2));
                float mnew = fmaxf(mrow[h2], mt);
                float alpha = __expf(mrow[h2] - mnew);
                float rs = 0.0f;
#pragma unroll
                for (int nt = 0; nt < 8; nt++) {
                    s[nt][2 * h2]     = __expf(s[nt][2 * h2] - mnew);
                    s[nt][2 * h2 + 1] = __expf(s[nt][2 * h2 + 1] - mnew);
                    rs += s[nt][2 * h2] + s[nt][2 * h2 + 1];
                }
                rs += __shfl_xor_sync(0xffffffffu, rs, 1);
                rs += __shfl_xor_sync(0xffffffffu, rs, 2);
                lrow[h2] = lrow[h2] * alpha + rs;
                mrow[h2] = mnew;
#pragma unroll
                for (int dt = 0; dt < 8; dt++) {
                    o[dt][2 * h2] *= alpha;
                    o[dt][2 * h2 + 1] *= alpha;
                }
            }

            // ---- O += P(half) V(half) ----
#pragma unroll
            for (int ksp = 0; ksp < 4; ksp++) {
                int t0 = 2 * ksp, t1 = 2 * ksp + 1;
                uint32_t ah[4];
                ah[0] = packh(s[t0][0], s[t0][1]);
                ah[1] = packh(s[t0][2], s[t0][3]);
                ah[2] = packh(s[t1][0], s[t1][1]);
                ah[3] = packh(s[t1][2], s[t1][3]);
#pragma unroll
                for (int ntv = 0; ntv < 4; ntv++) {
                    int row = ntv * 16 + (lane & 15);
                    int cch = hf * 8 + ksp * 2 + (lane >> 4);
                    uint32_t off = row * 256 + ((cch ^ (row & 7)) << 4);
                    uint32_t t[4], vh0[2], vh1[2];
                    ldsm4(t, sbase + 16384 + off);
                    vh0[0] = t[0]; vh0[1] = t[2]; vh1[0] = t[1]; vh1[1] = t[3];
                    mma16816(o[2 * ntv], ah, vh0);
                    mma16816(o[2 * ntv + 1], ah, vh1);
                }
            }
        }
    }

    // ---- normalize, write y (single fp16) ----
    float i0 = 1.0f / lrow[0], i1 = 1.0f / lrow[1];
    int r0 = bb * Tt + q0 + warp * 16 + (lane >> 2), r1 = r0 + 8;
#pragma unroll
    for (int dt = 0; dt < 8; dt++) {
        int col = hh * 64 + dt * 8 + 2 * (lane & 3);
        *reinterpret_cast<uint32_t*>(gy_h + (size_t)r0 * Cc + col) =
            packh(o[dt][0] * i0, o[dt][1] * i0);
        *reinterpret_cast<uint32_t*>(gy_h + (size_t)r1 * Cc + col) =
            packh(o[dt][2] * i1, o[dt][3] * i1);
    }
}

// ---------------------------------------------------------------------------
extern "C" void kernel_launch(void* const* d_in, const int* in_sizes, int n_in,
                              void* d_out, int out_size)
{
    (void)in_sizes; (void)n_in; (void)out_size;
    const float* x      = (const float*)d_in[0];
    const int*   pad    = (const int*)d_in[1];
    const float* w_attn = (const float*)d_in[2];
    const float* w_proj = (const float*)d_in[3];
    const float* b_proj = (const float*)d_in[4];
    float* out = (float*)d_out;

    cudaFuncSetAttribute(sa_gemm_mma<0>, cudaFuncAttributeMaxDynamicSharedMemorySize, GSM_BYTES);
    cudaFuncSetAttribute(sa_gemm_mma<1>, cudaFuncAttributeMaxDynamicSharedMemorySize, GSM_BYTES);
    cudaFuncSetAttribute(sa_attn_mma,    cudaFuncAttributeMaxDynamicSharedMemorySize, ASM_BYTES);

    void *pxh, *pyh, *pwah, *pwph;
    cudaGetSymbolAddress(&pxh, gx_h);
    cudaGetSymbolAddress(&pyh, gy_h);
    cudaGetSymbolAddress(&pwah, gwa_h);
    cudaGetSymbolAddress(&pwph, gwp_h);

    k_half<<<(BT * Kd / 4 + 255) / 256, 256>>>(
        (const float4*)x, (__half2*)pxh, BT * Kd / 4);
    k_splitT<<<dim3(3072 / 32, Kd / 32), dim3(32, 8)>>>(w_attn, (__half*)pwah, 3072);
    k_splitT<<<dim3(1024 / 32, Kd / 32), dim3(32, 8)>>>(w_proj, (__half*)pwph, 1024);

    sa_gemm_mma<0><<<dim3(3072 / 128, BT / 128), 256, GSM_BYTES>>>(
        (const __half*)pxh, (const __half*)pwah, nullptr, nullptr, 3072);

    sa_attn_mma<<<dim3(Tt / 128, Bb * Hh), 256, ASM_BYTES>>>(pad);

    sa_gemm_mma<1><<<dim3(1024 / 128, BT / 128), 256, GSM_BYTES>>>(
        (const __half*)pyh, (const __half*)pwph, b_proj, out, 1024);
}

// round 15
// speedup vs baseline: 1.0134x; 1.0134x over previous
#include <cuda_runtime.h>
#include <cuda_fp16.h>
#include <cstdint>

typedef unsigned long long u64;

__device__ __forceinline__ uint32_t smem_u32(const void* p) {
    uint32_t a;
    asm("{ .reg .u64 t; cvta.to.shared.u64 t, %1; cvt.u32.u64 %0, t; }" : "=r"(a) : "l"(p));
    return a;
}
__device__ __forceinline__ void ldsm4(uint32_t* r, uint32_t addr) {
    asm volatile("ldmatrix.sync.aligned.m8n8.x4.shared.b16 {%0,%1,%2,%3}, [%4];"
                 : "=r"(r[0]), "=r"(r[1]), "=r"(r[2]), "=r"(r[3]) : "r"(addr));
}
__device__ __forceinline__ void mma16816(float* d, const uint32_t* a, const uint32_t* b) {
    asm volatile(
        "mma.sync.aligned.m16n8k16.row.col.f32.f16.f16.f32 "
        "{%0,%1,%2,%3}, {%4,%5,%6,%7}, {%8,%9}, {%0,%1,%2,%3};"
        : "+f"(d[0]), "+f"(d[1]), "+f"(d[2]), "+f"(d[3])
        : "r"(a[0]), "r"(a[1]), "r"(a[2]), "r"(a[3]), "r"(b[0]), "r"(b[1]));
}
__device__ __forceinline__ void cpasync16(uint32_t dst, const void* src) {
    asm volatile("cp.async.cg.shared.global [%0], [%1], 16;" :: "r"(dst), "l"(src));
}
#define CP_COMMIT() asm volatile("cp.async.commit_group;" ::: "memory")
#define CP_WAIT1()  asm volatile("cp.async.wait_group 1;" ::: "memory")
#define CP_WAIT0()  asm volatile("cp.async.wait_group 0;" ::: "memory")

// pack 2 floats -> half2 bits (lo in low half)
__device__ __forceinline__ uint32_t packh(float lo, float hi) {
    __half2 h = __floats2half2_rn(lo, hi);
    return *reinterpret_cast<uint32_t*>(&h);
}

// ---------------- problem constants ----------------
constexpr int Bb = 4, Tt = 2048, Cc = 1024, Hh = 16, HD = 64;
constexpr int BT = Bb * Tt;
constexpr int Kd = 1024;
// GEMM: single-term fp16, BK=64, 2 tiles (A, B) x 16KB; 3-stage pipeline = 96KB, 2 CTAs/SM
constexpr int GTILE = 16384;
constexpr int STAGE = 2 * GTILE;       // 32768
constexpr int GSM_BYTES = 3 * STAGE;   // 98304
constexpr int ASTAGE = 32768;          // attn: Kh (16KB) + Vth (16KB)
constexpr int ASM_BYTES = 2 * ASTAGE;  // 64KB

// ---------------- scratch (device globals) ----------------
constexpr size_t QKV = (size_t)Bb * Hh * Tt * HD;   // 8388608
__device__ __half g_qh[QKV];                        // [b,h,t,d], pre-scaled 0.125
__device__ __half g_kh[QKV];                        // [b,h,t,d]
__device__ __half g_vth[QKV];                       // [b,h,d,t] (transposed)
__device__ __half gx_h[(size_t)BT * Kd];            // x single fp16
__device__ __half gy_h[(size_t)BT * Kd];            // y single fp16
__device__ __half gwa_h[(size_t)3072 * Kd];
__device__ __half gwp_h[(size_t)1024 * Kd];

// ---------------- conversion kernels ----------------
__global__ void k_half(const float4* __restrict__ src, __half2* __restrict__ h, int n4)
{
    int i = blockIdx.x * blockDim.x + threadIdx.x;
    if (i >= n4) return;
    float4 v = src[i];
    h[i * 2]     = __floats2half2_rn(v.x, v.y);
    h[i * 2 + 1] = __floats2half2_rn(v.z, v.w);
}

__global__ void k_splitT(const float* __restrict__ src, __half* __restrict__ h, int Ncols)
{
    __shared__ float ts[32][33];
    int tx = threadIdx.x, ty = threadIdx.y;
    int c0 = blockIdx.x * 32, r0 = blockIdx.y * 32;
#pragma unroll
    for (int i = 0; i < 4; i++)
        ts[ty + i * 8][tx] = src[(size_t)(r0 + ty + i * 8) * Ncols + c0 + tx];
    __syncthreads();
#pragma unroll
    for (int i = 0; i < 4; i++) {
        int n = c0 + ty + i * 8, k = r0 + tx;
        h[(size_t)n * 1024 + k] = __float2half_rn(ts[tx][ty + i * 8]);
    }
}

// ---------------------------------------------------------------------------
// fp16 single-term GEMM: D = A*B^T. BK=64, 128B-pitch, 0x70 swizzle,
// 3-stage cp.async pipeline, 2 CTAs/SM.
// MODE 0: q (scaled) and k single fp16 [b,h,t,d]; V^T single via smem transpose.
// MODE 1: fp32 out + bias.
// ---------------------------------------------------------------------------
template <int MODE>
__global__ __launch_bounds__(256, 2) void sa_gemm_mma(
    const __half* __restrict__ A, const __half* __restrict__ B,
    const float* __restrict__ bias, float* __restrict__ out, int N)
{
    extern __shared__ char smem[];
    uint32_t sb = smem_u32(smem);
    int tid = threadIdx.x, lane = tid & 31, warp = tid >> 5;
    int m0 = blockIdx.y * 128, n0 = blockIdx.x * 128;
    int wm = (warp >> 2) * 64, wn = (warp & 3) * 32;

    auto load_stage = [&](int st, int c) {
        uint32_t sbase = sb + st * STAGE;
        int kc0 = c * 64;
#pragma unroll
        for (int i = 0; i < 8; i++) {
            int id = tid + i * 256;            // 2048 16B chunks
            int tile = id >> 10, rem = id & 1023;
            int row = rem >> 3, cch = rem & 7;
            const __half* src = (tile ? B : A) + (size_t)((tile ? n0 : m0) + row) * Kd + kc0 + cch * 8;
            uint32_t off = row * 128 + cch * 16;
            off ^= ((off >> 3) & 0x70);
            cpasync16(sbase + tile * GTILE + off, src);
        }
    };

    float acc[4][4][4];
#pragma unroll
    for (int a = 0; a < 4; a++)
#pragma unroll
        for (int b = 0; b < 4; b++)
#pragma unroll
            for (int e = 0; e < 4; e++) acc[a][b][e] = 0.0f;

    load_stage(0, 0);
    CP_COMMIT();
    load_stage(1, 1);
    CP_COMMIT();

    for (int c = 0; c < 16; c++) {
        if (c < 15) { CP_WAIT1(); } else { CP_WAIT0(); }   // stage c landed
        __syncthreads();                      // all warps done with reused buffer
        if (c + 2 < 16) { load_stage((c + 2) % 3, c + 2); CP_COMMIT(); }
        uint32_t sbase = sb + (c % 3) * STAGE;
#pragma unroll
        for (int ks = 0; ks < 4; ks++) {
            uint32_t ah[4][4], bhf[4][2];
#pragma unroll
            for (int mt = 0; mt < 4; mt++) {
                int row = wm + mt * 16 + (lane & 15);
                int cch = ks * 2 + (lane >> 4);
                uint32_t off = row * 128 + cch * 16;
                off ^= ((off >> 3) & 0x70);
                ldsm4(ah[mt], sbase + off);
            }
#pragma unroll
            for (int nt = 0; nt < 2; nt++) {
                int row = wn + nt * 16 + (lane & 15);
                int cch = ks * 2 + (lane >> 4);
                uint32_t off = row * 128 + cch * 16;
                off ^= ((off >> 3) & 0x70);
                uint32_t t[4];
                ldsm4(t, sbase + GTILE + off);
                bhf[nt * 2][0] = t[0]; bhf[nt * 2][1] = t[2];
                bhf[nt * 2 + 1][0] = t[1]; bhf[nt * 2 + 1][1] = t[3];
            }
#pragma unroll
            for (int mt = 0; mt < 4; mt++)
#pragma unroll
                for (int j = 0; j < 4; j++)
                    mma16816(acc[mt][j], ah[mt], bhf[j]);
        }
    }
    __syncthreads();

    if (MODE == 0 && n0 >= 2048) {
        // ---- V CTA: smem-staged transpose -> coalesced [b,h,d,t] stores ----
        constexpr int PITCH = 136;
        __half* svh = reinterpret_cast<__half*>(smem);
        int bidx = m0 >> 11, tbase = m0 & 2047;
#pragma unroll
        for (int hl = 0; hl < 2; hl++) {
            if (hl) __syncthreads();
#pragma unroll
            for (int mt = 0; mt < 4; mt++)
#pragma unroll
                for (int j = 0; j < 4; j++) {
                    int n = n0 + wn + j * 8 + (lane & 3) * 2;
                    if (((n >> 6) & 1) != hl) continue;
                    int dd = n & 63;
#pragma unroll
                    for (int half = 0; half < 2; half++) {
                        int tl = wm + mt * 16 + (lane >> 2) + half * 8;
                        svh[dd * PITCH + tl]       = __float2half_rn(acc[mt][j][half * 2]);
                        svh[(dd + 1) * PITCH + tl] = __float2half_rn(acc[mt][j][half * 2 + 1]);
                    }
                }
            __syncthreads();
            int h = ((n0 & 1023) >> 6) + hl;
            int bhn = bidx * 16 + h;
#pragma unroll
            for (int i = 0; i < 4; i++) {
                int id = tid + i * 256;          // 1024: 64 dd x 16 tc
                int dd = id >> 4, tc = id & 15;
                uint4 v = *reinterpret_cast<const uint4*>(svh + dd * PITCH + tc * 8);
                *reinterpret_cast<uint4*>(g_vth +
                    (((size_t)bhn * HD + dd) * Tt + tbase + tc * 8)) = v;
            }
        }
        return;
    }

#pragma unroll
    for (int mt = 0; mt < 4; mt++)
#pragma unroll
        for (int j = 0; j < 4; j++) {
            int n = n0 + wn + j * 8 + (lane & 3) * 2;
            int mA = m0 + wm + mt * 16 + (lane >> 2);
#pragma unroll
            for (int half = 0; half < 2; half++) {
                int m = mA + half * 8;
                float f0 = acc[mt][j][half * 2], f1 = acc[mt][j][half * 2 + 1];
                if (MODE == 0) {
                    int part = n >> 10, c1 = n & 1023, h = c1 >> 6, dd = c1 & 63;
                    int bidx = m >> 11, t = m & 2047;
                    int bhn = bidx * 16 + h;
                    size_t idx = ((size_t)bhn * Tt + t) * HD + dd;
                    if (part == 0) {
                        *reinterpret_cast<uint32_t*>(g_qh + idx) =
                            packh(f0 * 0.125f, f1 * 0.125f);
                    } else {
                        *reinterpret_cast<uint32_t*>(g_kh + idx) = packh(f0, f1);
                    }
                } else {
                    f0 += __ldg(bias + n);
                    f1 += __ldg(bias + n + 1);
                    float2 v = {f0, f1};
                    *reinterpret_cast<float2*>(out + (size_t)m * N + n) = v;
                }
            }
        }
}

// ---------------------------------------------------------------------------
// Pure-fp16 tensor-core flash attention (round-13 verified best).
// Single-sync double-buffered mainloop, s[16][4], 1 CTA/SM.
// S = Qh*Kh^T (1 mma); O += Ph*Vh (1 mma). Writes y single fp16.
// ---------------------------------------------------------------------------
__global__ __launch_bounds__(256, 1) void sa_attn_mma(const int* __restrict__ pad)
{
    extern __shared__ char smem[];
    __shared__ float pm[2][128];
    uint32_t sb = smem_u32(smem);
    int tid = threadIdx.x, lane = tid & 31, warp = tid >> 5;
    int qt = (int)gridDim.x - 1 - (int)blockIdx.x;   // big tiles first
    int bh = blockIdx.y, bb = bh >> 4, hh = bh & 15;
    int q0 = qt * 128;
    size_t kbase = (size_t)bh * Tt * HD;
    size_t vbase = (size_t)bh * HD * Tt;

    // ---- stage Q (single fp16), extract fragments ----
#pragma unroll
    for (int i = 0; i < 4; i++) {
        int id = tid + i * 256;            // 1024: 128 rows x 8 chunks
        int row = id >> 3, c = id & 7;
        const __half* src = g_qh + kbase + (size_t)(q0 + row) * HD + c * 8;
        cpasync16(sb + row * 128 + ((c ^ (row & 7)) << 4), src);
    }
    CP_COMMIT();
    CP_WAIT0();
    __syncthreads();
    uint32_t qh[4][4];
#pragma unroll
    for (int ks = 0; ks < 4; ks++) {
        int row = warp * 16 + (lane & 15), cch = ks * 2 + (lane >> 4);
        uint32_t off = row * 128 + ((cch ^ (row & 7)) << 4);
        ldsm4(qh[ks], sb + off);
    }
    __syncthreads();

    auto load_stage = [&](int st, int kt) {
        uint32_t sbase = sb + st * ASTAGE;
        int k0 = kt * 128;
#pragma unroll
        for (int i = 0; i < 8; i++) {
            int id = tid + i * 256;
            int part = id >> 10, rem = id & 1023;
            if (part == 0) {
                int row = rem >> 3, c = rem & 7;
                const __half* src = g_kh + kbase + (size_t)(k0 + row) * HD + c * 8;
                cpasync16(sbase + row * 128 + ((c ^ (row & 7)) << 4), src);
            } else {
                int row = rem >> 4, c = rem & 15;
                const __half* src = g_vth + vbase + (size_t)row * Tt + k0 + c * 8;
                cpasync16(sbase + 16384 + row * 256 + ((c ^ (row & 7)) << 4), src);
            }
        }
        if (tid < 128) pm[st][tid] = pad[bb * Tt + k0 + tid] ? 0.0f : -1e30f;
    };

    float o[8][4];
#pragma unroll
    for (int i = 0; i < 8; i++)
#pragma unroll
        for (int e = 0; e < 4; e++) o[i][e] = 0.0f;
    float mrow[2] = {-1e30f, -1e30f}, lrow[2] = {0.0f, 0.0f};

    load_stage(0, 0);
    CP_COMMIT();

    for (int kt = 0; kt <= qt; kt++) {
        CP_WAIT0();
        __syncthreads();                     // all warps done with prev buffer
        if (kt < qt) { load_stage((kt + 1) & 1, kt + 1); CP_COMMIT(); }
        uint32_t sbase = sb + (kt & 1) * ASTAGE;

        // ---- S = Q K^T (single-term) ----
        float s[16][4];
#pragma unroll
        for (int nt = 0; nt < 16; nt++)
#pragma unroll
            for (int e = 0; e < 4; e++) s[nt][e] = 0.0f;

#pragma unroll
        for (int ntp = 0; ntp < 8; ntp++) {
#pragma unroll
            for (int ks = 0; ks < 4; ks++) {
                int row = ntp * 16 + (lane & 15), cch = ks * 2 + (lane >> 4);
                uint32_t off = row * 128 + ((cch ^ (row & 7)) << 4);
                uint32_t t[4], kh0[2], kh1[2];
                ldsm4(t, sbase + off);
                kh0[0] = t[0]; kh0[1] = t[2]; kh1[0] = t[1]; kh1[1] = t[3];
                mma16816(s[2 * ntp], qh[ks], kh0);
                mma16816(s[2 * ntp + 1], qh[ks], kh1);
            }
        }

        // ---- masks ----
        int c2 = 2 * (lane & 3);
#pragma unroll
        for (int nt = 0; nt < 16; nt++) {
            float m0v = pm[kt & 1][nt * 8 + c2];
            float m1v = pm[kt & 1][nt * 8 + c2 + 1];
            s[nt][0] += m0v; s[nt][1] += m1v; s[nt][2] += m0v; s[nt][3] += m1v;
        }
        if (kt == qt) {
            int r0 = warp * 16 + (lane >> 2), r1 = r0 + 8;
#pragma unroll
            for (int nt = 0; nt < 16; nt++) {
                int col0 = nt * 8 + c2;
                if (col0 > r0)     s[nt][0] = -1e30f;
                if (col0 + 1 > r0) s[nt][1] = -1e30f;
                if (col0 > r1)     s[nt][2] = -1e30f;
                if (col0 + 1 > r1) s[nt][3] = -1e30f;
            }
        }

        // ---- online softmax (2 rows per lane) ----
#pragma unroll
        for (int h2 = 0; h2 < 2; h2++) {
            float mt = -1e30f;
#pragma unroll
            for (int nt = 0; nt < 16; nt++)
                mt = fmaxf(mt, fmaxf(s[nt][2 * h2], s[nt][2 * h2 + 1]));
            mt = fmaxf(mt, __shfl_xor_sync(0xffffffffu, mt, 1));
            mt = fmaxf(mt, __shfl_xor_sync(0xffffffffu, mt, 2));
            float mnew = fmaxf(mrow[h2], mt);
            float alpha = __expf(mrow[h2] - mnew);
            float rs = 0.0f;
#pragma unroll
            for (int nt = 0; nt < 16; nt++) {
                s[nt][2 * h2]     = __expf(s[nt][2 * h2] - mnew);
                s[nt][2 * h2 + 1] = __expf(s[nt][2 * h2 + 1] - mnew);
                rs += s[nt][2 * h2] + s[nt][2 * h2 + 1];
            }
            rs += __shfl_xor_sync(0xffffffffu, rs, 1);
            rs += __shfl_xor_sync(0xffffffffu, rs, 2);
            lrow[h2] = lrow[h2] * alpha + rs;
            mrow[h2] = mnew;
#pragma unroll
            for (int dt = 0; dt < 8; dt++) {
                o[dt][2 * h2] *= alpha;
                o[dt][2 * h2 + 1] *= alpha;
            }
        }

        // ---- O += P V (single-term) ----
#pragma unroll
        for (int ksp = 0; ksp < 8; ksp++) {
            int t0 = 2 * ksp, t1 = 2 * ksp + 1;
            uint32_t ah[4];
            ah[0] = packh(s[t0][0], s[t0][1]);
            ah[1] = packh(s[t0][2], s[t0][3]);
            ah[2] = packh(s[t1][0], s[t1][1]);
            ah[3] = packh(s[t1][2], s[t1][3]);
#pragma unroll
            for (int ntv = 0; ntv < 4; ntv++) {
                int row = ntv * 16 + (lane & 15), cch = ksp * 2 + (lane >> 4);
                uint32_t off = row * 256 + ((cch ^ (row & 7)) << 4);
                uint32_t t[4], vh0[2], vh1[2];
                ldsm4(t, sbase + 16384 + off);
                vh0[0] = t[0]; vh0[1] = t[2]; vh1[0] = t[1]; vh1[1] = t[3];
                mma16816(o[2 * ntv], ah, vh0);
                mma16816(o[2 * ntv + 1], ah, vh1);
            }
        }
    }

    // ---- normalize, write y (single fp16) ----
    float i0 = 1.0f / lrow[0], i1 = 1.0f / lrow[1];
    int r0 = bb * Tt + q0 + warp * 16 + (lane >> 2), r1 = r0 + 8;
#pragma unroll
    for (int dt = 0; dt < 8; dt++) {
        int col = hh * 64 + dt * 8 + 2 * (lane & 3);
        *reinterpret_cast<uint32_t*>(gy_h + (size_t)r0 * Cc + col) =
            packh(o[dt][0] * i0, o[dt][1] * i0);
        *reinterpret_cast<uint32_t*>(gy_h + (size_t)r1 * Cc + col) =
            packh(o[dt][2] * i1, o[dt][3] * i1);
    }
}

// ---------------------------------------------------------------------------
extern "C" void kernel_launch(void* const* d_in, const int* in_sizes, int n_in,
                              void* d_out, int out_size)
{
    (void)in_sizes; (void)n_in; (void)out_size;
    const float* x      = (const float*)d_in[0];
    const int*   pad    = (const int*)d_in[1];
    const float* w_attn = (const float*)d_in[2];
    const float* w_proj = (const float*)d_in[3];
    const float* b_proj = (const float*)d_in[4];
    float* out = (float*)d_out;

    cudaFuncSetAttribute(sa_gemm_mma<0>, cudaFuncAttributeMaxDynamicSharedMemorySize, GSM_BYTES);
    cudaFuncSetAttribute(sa_gemm_mma<1>, cudaFuncAttributeMaxDynamicSharedMemorySize, GSM_BYTES);
    cudaFuncSetAttribute(sa_attn_mma,    cudaFuncAttributeMaxDynamicSharedMemorySize, ASM_BYTES);

    void *pxh, *pyh, *pwah, *pwph;
    cudaGetSymbolAddress(&pxh, gx_h);
    cudaGetSymbolAddress(&pyh, gy_h);
    cudaGetSymbolAddress(&pwah, gwa_h);
    cudaGetSymbolAddress(&pwph, gwp_h);

    k_half<<<(BT * Kd / 4 + 255) / 256, 256>>>(
        (const float4*)x, (__half2*)pxh, BT * Kd / 4);
    k_splitT<<<dim3(3072 / 32, Kd / 32), dim3(32, 8)>>>(w_attn, (__half*)pwah, 3072);
    k_splitT<<<dim3(1024 / 32, Kd / 32), dim3(32, 8)>>>(w_proj, (__half*)pwph, 1024);

    sa_gemm_mma<0><<<dim3(3072 / 128, BT / 128), 256, GSM_BYTES>>>(
        (const __half*)pxh, (const __half*)pwah, nullptr, nullptr, 3072);

    sa_attn_mma<<<dim3(Tt / 128, Bb * Hh), 256, ASM_BYTES>>>(pad);

    sa_gemm_mma<1><<<dim3(1024 / 128, BT / 128), 256, GSM_BYTES>>>(
        (const __half*)pyh, (const __half*)pwph, b_proj, out, 1024);
}

// round 16
// speedup vs baseline: 1.0506x; 1.0367x over previous
#include <cuda_runtime.h>
#include <cuda_fp16.h>
#include <cstdint>

typedef unsigned long long u64;

__device__ __forceinline__ uint32_t smem_u32(const void* p) {
    uint32_t a;
    asm("{ .reg .u64 t; cvta.to.shared.u64 t, %1; cvt.u32.u64 %0, t; }" : "=r"(a) : "l"(p));
    return a;
}
__device__ __forceinline__ void ldsm4(uint32_t* r, uint32_t addr) {
    asm volatile("ldmatrix.sync.aligned.m8n8.x4.shared.b16 {%0,%1,%2,%3}, [%4];"
                 : "=r"(r[0]), "=r"(r[1]), "=r"(r[2]), "=r"(r[3]) : "r"(addr));
}
__device__ __forceinline__ void mma16816(float* d, const uint32_t* a, const uint32_t* b) {
    asm volatile(
        "mma.sync.aligned.m16n8k16.row.col.f32.f16.f16.f32 "
        "{%0,%1,%2,%3}, {%4,%5,%6,%7}, {%8,%9}, {%0,%1,%2,%3};"
        : "+f"(d[0]), "+f"(d[1]), "+f"(d[2]), "+f"(d[3])
        : "r"(a[0]), "r"(a[1]), "r"(a[2]), "r"(a[3]), "r"(b[0]), "r"(b[1]));
}
__device__ __forceinline__ void cpasync16(uint32_t dst, const void* src) {
    asm volatile("cp.async.cg.shared.global [%0], [%1], 16;" :: "r"(dst), "l"(src));
}
#define CP_COMMIT() asm volatile("cp.async.commit_group;" ::: "memory")
#define CP_WAIT1()  asm volatile("cp.async.wait_group 1;" ::: "memory")
#define CP_WAIT0()  asm volatile("cp.async.wait_group 0;" ::: "memory")

// pack 2 floats -> half2 bits (lo in low half)
__device__ __forceinline__ uint32_t packh(float lo, float hi) {
    __half2 h = __floats2half2_rn(lo, hi);
    return *reinterpret_cast<uint32_t*>(&h);
}

// ---------------- problem constants ----------------
constexpr int Bb = 4, Tt = 2048, Cc = 1024, Hh = 16, HD = 64;
constexpr int BT = Bb * Tt;
constexpr int Kd = 1024;
// GEMM: single-term fp16, BK=64, 2 tiles (A, B) x 16KB; double buffer = 64KB, 2 CTAs/SM
constexpr int GTILE = 16384;
constexpr int STAGE = 2 * GTILE;       // 32768
constexpr int GSM_BYTES = 2 * STAGE;   // 65536
constexpr int ASTAGE = 32768;          // attn: Kh (16KB) + Vth (16KB)
constexpr int ASM_BYTES = 2 * ASTAGE;  // 64KB

// ---------------- scratch (device globals) ----------------
constexpr size_t QKV = (size_t)Bb * Hh * Tt * HD;   // 8388608
__device__ __half g_qh[QKV];                        // [b,h,t,d], pre-scaled 0.125
__device__ __half g_kh[QKV];                        // [b,h,t,d]
__device__ __half g_vth[QKV];                       // [b,h,d,t] (transposed)
__device__ __half gx_h[(size_t)BT * Kd];            // x single fp16
__device__ __half gy_h[(size_t)BT * Kd];            // y single fp16
__device__ __half gwa_h[(size_t)3072 * Kd];
__device__ __half gwp_h[(size_t)1024 * Kd];

// ---------------------------------------------------------------------------
// Fused conversion kernel (one launch):
//   blocks [0, XB)            : x fp32 -> fp16            (flat 256)
//   blocks [XB, XB+WAB)       : w_attn transpose -> fp16  (32x8 from flat tid)
//   blocks [XB+WAB, +WPB)     : w_proj transpose -> fp16
// ---------------------------------------------------------------------------
constexpr int XB  = (BT * Kd / 4) / 256;            // 8192 blocks
constexpr int WAB = (3072 / 32) * (Kd / 32);        // 96*32 = 3072 blocks
constexpr int WPB = (1024 / 32) * (Kd / 32);        // 32*32 = 1024 blocks

__global__ __launch_bounds__(256) void k_convert(
    const float4* __restrict__ x4,
    const float* __restrict__ wa, const float* __restrict__ wp)
{
    int b = blockIdx.x, tid = threadIdx.x;
    if (b < XB) {
        int i = b * 256 + tid;
        float4 v = x4[i];
        __half2* h = reinterpret_cast<__half2*>(gx_h);
        h[i * 2]     = __floats2half2_rn(v.x, v.y);
        h[i * 2 + 1] = __floats2half2_rn(v.z, v.w);
        return;
    }
    // transpose branch
    const float* src;
    __half* dst;
    int Ncols, bx;
    if (b < XB + WAB) {
        src = wa; dst = gwa_h; Ncols = 3072; bx = b - XB;
    } else {
        src = wp; dst = gwp_h; Ncols = 1024; bx = b - XB - WAB;
    }
    int nbx = Ncols / 32;
    int c0 = (bx % nbx) * 32, r0 = (bx / nbx) * 32;
    int tx = tid & 31, ty = tid >> 5;
    __shared__ float ts[32][33];
#pragma unroll
    for (int i = 0; i < 4; i++)
        ts[ty + i * 8][tx] = src[(size_t)(r0 + ty + i * 8) * Ncols + c0 + tx];
    __syncthreads();
#pragma unroll
    for (int i = 0; i < 4; i++) {
        int n = c0 + ty + i * 8, k = r0 + tx;
        dst[(size_t)n * 1024 + k] = __float2half_rn(ts[tx][ty + i * 8]);
    }
}

// ---------------------------------------------------------------------------
// fp16 single-term GEMM (round-13 verified): D = A*B^T. BK=64, 128B-pitch,
// 0x70 swizzle, cp.async double-buffered, 2 CTAs/SM.
// MODE 0: q (scaled) and k single fp16 [b,h,t,d]; V^T single via smem transpose.
// MODE 1: fp32 out + bias.
// ---------------------------------------------------------------------------
template <int MODE>
__global__ __launch_bounds__(256, 2) void sa_gemm_mma(
    const __half* __restrict__ A, const __half* __restrict__ B,
    const float* __restrict__ bias, float* __restrict__ out, int N)
{
    extern __shared__ char smem[];
    uint32_t sb = smem_u32(smem);
    int tid = threadIdx.x, lane = tid & 31, warp = tid >> 5;
    int m0 = blockIdx.y * 128, n0 = blockIdx.x * 128;
    int wm = (warp >> 2) * 64, wn = (warp & 3) * 32;

    auto load_stage = [&](int st, int c) {
        uint32_t sbase = sb + st * STAGE;
        int kc0 = c * 64;
#pragma unroll
        for (int i = 0; i < 8; i++) {
            int id = tid + i * 256;            // 2048 16B chunks
            int tile = id >> 10, rem = id & 1023;
            int row = rem >> 3, cch = rem & 7;
            const __half* src = (tile ? B : A) + (size_t)((tile ? n0 : m0) + row) * Kd + kc0 + cch * 8;
            uint32_t off = row * 128 + cch * 16;
            off ^= ((off >> 3) & 0x70);
            cpasync16(sbase + tile * GTILE + off, src);
        }
    };

    float acc[4][4][4];
#pragma unroll
    for (int a = 0; a < 4; a++)
#pragma unroll
        for (int b = 0; b < 4; b++)
#pragma unroll
            for (int e = 0; e < 4; e++) acc[a][b][e] = 0.0f;

    load_stage(0, 0);
    CP_COMMIT();

    for (int c = 0; c < 16; c++) {
        if (c + 1 < 16) load_stage((c + 1) & 1, c + 1);
        CP_COMMIT();
        CP_WAIT1();
        __syncthreads();
        uint32_t sbase = sb + (c & 1) * STAGE;
#pragma unroll
        for (int ks = 0; ks < 4; ks++) {
            uint32_t ah[4][4], bhf[4][2];
#pragma unroll
            for (int mt = 0; mt < 4; mt++) {
                int row = wm + mt * 16 + (lane & 15);
                int cch = ks * 2 + (lane >> 4);
                uint32_t off = row * 128 + cch * 16;
                off ^= ((off >> 3) & 0x70);
                ldsm4(ah[mt], sbase + off);
            }
#pragma unroll
            for (int nt = 0; nt < 2; nt++) {
                int row = wn + nt * 16 + (lane & 15);
                int cch = ks * 2 + (lane >> 4);
                uint32_t off = row * 128 + cch * 16;
                off ^= ((off >> 3) & 0x70);
                uint32_t t[4];
                ldsm4(t, sbase + GTILE + off);
                bhf[nt * 2][0] = t[0]; bhf[nt * 2][1] = t[2];
                bhf[nt * 2 + 1][0] = t[1]; bhf[nt * 2 + 1][1] = t[3];
            }
#pragma unroll
            for (int mt = 0; mt < 4; mt++)
#pragma unroll
                for (int j = 0; j < 4; j++)
                    mma16816(acc[mt][j], ah[mt], bhf[j]);
        }
        __syncthreads();
    }

    if (MODE == 0 && n0 >= 2048) {
        // ---- V CTA: smem-staged transpose -> coalesced [b,h,d,t] stores ----
        constexpr int PITCH = 136;
        __half* svh = reinterpret_cast<__half*>(smem);
        int bidx = m0 >> 11, tbase = m0 & 2047;
#pragma unroll
        for (int hl = 0; hl < 2; hl++) {
            if (hl) __syncthreads();
#pragma unroll
            for (int mt = 0; mt < 4; mt++)
#pragma unroll
                for (int j = 0; j < 4; j++) {
                    int n = n0 + wn + j * 8 + (lane & 3) * 2;
                    if (((n >> 6) & 1) != hl) continue;
                    int dd = n & 63;
#pragma unroll
                    for (int half = 0; half < 2; half++) {
                        int tl = wm + mt * 16 + (lane >> 2) + half * 8;
                        svh[dd * PITCH + tl]       = __float2half_rn(acc[mt][j][half * 2]);
                        svh[(dd + 1) * PITCH + tl] = __float2half_rn(acc[mt][j][half * 2 + 1]);
                    }
                }
            __syncthreads();
            int h = ((n0 & 1023) >> 6) + hl;
            int bhn = bidx * 16 + h;
#pragma unroll
            for (int i = 0; i < 4; i++) {
                int id = tid + i * 256;          // 1024: 64 dd x 16 tc
                int dd = id >> 4, tc = id & 15;
                uint4 v = *reinterpret_cast<const uint4*>(svh + dd * PITCH + tc * 8);
                *reinterpret_cast<uint4*>(g_vth +
                    (((size_t)bhn * HD + dd) * Tt + tbase + tc * 8)) = v;
            }
        }
        return;
    }

#pragma unroll
    for (int mt = 0; mt < 4; mt++)
#pragma unroll
        for (int j = 0; j < 4; j++) {
            int n = n0 + wn + j * 8 + (lane & 3) * 2;
            int mA = m0 + wm + mt * 16 + (lane >> 2);
#pragma unroll
            for (int half = 0; half < 2; half++) {
                int m = mA + half * 8;
                float f0 = acc[mt][j][half * 2], f1 = acc[mt][j][half * 2 + 1];
                if (MODE == 0) {
                    int part = n >> 10, c1 = n & 1023, h = c1 >> 6, dd = c1 & 63;
                    int bidx = m >> 11, t = m & 2047;
                    int bhn = bidx * 16 + h;
                    size_t idx = ((size_t)bhn * Tt + t) * HD + dd;
                    if (part == 0) {
                        *reinterpret_cast<uint32_t*>(g_qh + idx) =
                            packh(f0 * 0.125f, f1 * 0.125f);
                    } else {
                        *reinterpret_cast<uint32_t*>(g_kh + idx) = packh(f0, f1);
                    }
                } else {
                    f0 += __ldg(bias + n);
                    f1 += __ldg(bias + n + 1);
                    float2 v = {f0, f1};
                    *reinterpret_cast<float2*>(out + (size_t)m * N + n) = v;
                }
            }
        }
}

// ---------------------------------------------------------------------------
// Pure-fp16 tensor-core flash attention (round-13 verified best).
// Single-sync double-buffered mainloop, s[16][4], 1 CTA/SM.
// S = Qh*Kh^T (1 mma); O += Ph*Vh (1 mma). Writes y single fp16.
// ---------------------------------------------------------------------------
__global__ __launch_bounds__(256, 1) void sa_attn_mma(const int* __restrict__ pad)
{
    extern __shared__ char smem[];
    __shared__ float pm[2][128];
    uint32_t sb = smem_u32(smem);
    int tid = threadIdx.x, lane = tid & 31, warp = tid >> 5;
    int qt = (int)gridDim.x - 1 - (int)blockIdx.x;   // big tiles first
    int bh = blockIdx.y, bb = bh >> 4, hh = bh & 15;
    int q0 = qt * 128;
    size_t kbase = (size_t)bh * Tt * HD;
    size_t vbase = (size_t)bh * HD * Tt;

    // ---- stage Q (single fp16), extract fragments ----
#pragma unroll
    for (int i = 0; i < 4; i++) {
        int id = tid + i * 256;            // 1024: 128 rows x 8 chunks
        int row = id >> 3, c = id & 7;
        const __half* src = g_qh + kbase + (size_t)(q0 + row) * HD + c * 8;
        cpasync16(sb + row * 128 + ((c ^ (row & 7)) << 4), src);
    }
    CP_COMMIT();
    CP_WAIT0();
    __syncthreads();
    uint32_t qh[4][4];
#pragma unroll
    for (int ks = 0; ks < 4; ks++) {
        int row = warp * 16 + (lane & 15), cch = ks * 2 + (lane >> 4);
        uint32_t off = row * 128 + ((cch ^ (row & 7)) << 4);
        ldsm4(qh[ks], sb + off);
    }
    __syncthreads();

    auto load_stage = [&](int st, int kt) {
        uint32_t sbase = sb + st * ASTAGE;
        int k0 = kt * 128;
#pragma unroll
        for (int i = 0; i < 8; i++) {
            int id = tid + i * 256;
            int part = id >> 10, rem = id & 1023;
            if (part == 0) {
                int row = rem >> 3, c = rem & 7;
                const __half* src = g_kh + kbase + (size_t)(k0 + row) * HD + c * 8;
                cpasync16(sbase + row * 128 + ((c ^ (row & 7)) << 4), src);
            } else {
                int row = rem >> 4, c = rem & 15;
                const __half* src = g_vth + vbase + (size_t)row * Tt + k0 + c * 8;
                cpasync16(sbase + 16384 + row * 256 + ((c ^ (row & 7)) << 4), src);
            }
        }
        if (tid < 128) pm[st][tid] = pad[bb * Tt + k0 + tid] ? 0.0f : -1e30f;
    };

    float o[8][4];
#pragma unroll
    for (int i = 0; i < 8; i++)
#pragma unroll
        for (int e = 0; e < 4; e++) o[i][e] = 0.0f;
    float mrow[2] = {-1e30f, -1e30f}, lrow[2] = {0.0f, 0.0f};

    load_stage(0, 0);
    CP_COMMIT();

    for (int kt = 0; kt <= qt; kt++) {
        CP_WAIT0();
        __syncthreads();                     // all warps done with prev buffer
        if (kt < qt) { load_stage((kt + 1) & 1, kt + 1); CP_COMMIT(); }
        uint32_t sbase = sb + (kt & 1) * ASTAGE;

        // ---- S = Q K^T (single-term) ----
        float s[16][4];
#pragma unroll
        for (int nt = 0; nt < 16; nt++)
#pragma unroll
            for (int e = 0; e < 4; e++) s[nt][e] = 0.0f;

#pragma unroll
        for (int ntp = 0; ntp < 8; ntp++) {
#pragma unroll
            for (int ks = 0; ks < 4; ks++) {
                int row = ntp * 16 + (lane & 15), cch = ks * 2 + (lane >> 4);
                uint32_t off = row * 128 + ((cch ^ (row & 7)) << 4);
                uint32_t t[4], kh0[2], kh1[2];
                ldsm4(t, sbase + off);
                kh0[0] = t[0]; kh0[1] = t[2]; kh1[0] = t[1]; kh1[1] = t[3];
                mma16816(s[2 * ntp], qh[ks], kh0);
                mma16816(s[2 * ntp + 1], qh[ks], kh1);
            }
        }

        // ---- masks ----
        int c2 = 2 * (lane & 3);
#pragma unroll
        for (int nt = 0; nt < 16; nt++) {
            float m0v = pm[kt & 1][nt * 8 + c2];
            float m1v = pm[kt & 1][nt * 8 + c2 + 1];
            s[nt][0] += m0v; s[nt][1] += m1v; s[nt][2] += m0v; s[nt][3] += m1v;
        }
        if (kt == qt) {
            int r0 = warp * 16 + (lane >> 2), r1 = r0 + 8;
#pragma unroll
            for (int nt = 0; nt < 16; nt++) {
                int col0 = nt * 8 + c2;
                if (col0 > r0)     s[nt][0] = -1e30f;
                if (col0 + 1 > r0) s[nt][1] = -1e30f;
                if (col0 > r1)     s[nt][2] = -1e30f;
                if (col0 + 1 > r1) s[nt][3] = -1e30f;
            }
        }

        // ---- online softmax (2 rows per lane) ----
#pragma unroll
        for (int h2 = 0; h2 < 2; h2++) {
            float mt = -1e30f;
#pragma unroll
            for (int nt = 0; nt < 16; nt++)
                mt = fmaxf(mt, fmaxf(s[nt][2 * h2], s[nt][2 * h2 + 1]));
            mt = fmaxf(mt, __shfl_xor_sync(0xffffffffu, mt, 1));
            mt = fmaxf(mt, __shfl_xor_sync(0xffffffffu, mt, 2));
            float mnew = fmaxf(mrow[h2], mt);
            float alpha = __expf(mrow[h2] - mnew);
            float rs = 0.0f;
#pragma unroll
            for (int nt = 0; nt < 16; nt++) {
                s[nt][2 * h2]     = __expf(s[nt][2 * h2] - mnew);
                s[nt][2 * h2 + 1] = __expf(s[nt][2 * h2 + 1] - mnew);
                rs += s[nt][2 * h2] + s[nt][2 * h2 + 1];
            }
            rs += __shfl_xor_sync(0xffffffffu, rs, 1);
            rs += __shfl_xor_sync(0xffffffffu, rs, 2);
            lrow[h2] = lrow[h2] * alpha + rs;
            mrow[h2] = mnew;
#pragma unroll
            for (int dt = 0; dt < 8; dt++) {
                o[dt][2 * h2] *= alpha;
                o[dt][2 * h2 + 1] *= alpha;
            }
        }

        // ---- O += P V (single-term) ----
#pragma unroll
        for (int ksp = 0; ksp < 8; ksp++) {
            int t0 = 2 * ksp, t1 = 2 * ksp + 1;
            uint32_t ah[4];
            ah[0] = packh(s[t0][0], s[t0][1]);
            ah[1] = packh(s[t0][2], s[t0][3]);
            ah[2] = packh(s[t1][0], s[t1][1]);
            ah[3] = packh(s[t1][2], s[t1][3]);
#pragma unroll
            for (int ntv = 0; ntv < 4; ntv++) {
                int row = ntv * 16 + (lane & 15), cch = ksp * 2 + (lane >> 4);
                uint32_t off = row * 256 + ((cch ^ (row & 7)) << 4);
                uint32_t t[4], vh0[2], vh1[2];
                ldsm4(t, sbase + 16384 + off);
                vh0[0] = t[0]; vh0[1] = t[2]; vh1[0] = t[1]; vh1[1] = t[3];
                mma16816(o[2 * ntv], ah, vh0);
                mma16816(o[2 * ntv + 1], ah, vh1);
            }
        }
    }

    // ---- normalize, write y (single fp16) ----
    float i0 = 1.0f / lrow[0], i1 = 1.0f / lrow[1];
    int r0 = bb * Tt + q0 + warp * 16 + (lane >> 2), r1 = r0 + 8;
#pragma unroll
    for (int dt = 0; dt < 8; dt++) {
        int col = hh * 64 + dt * 8 + 2 * (lane & 3);
        *reinterpret_cast<uint32_t*>(gy_h + (size_t)r0 * Cc + col) =
            packh(o[dt][0] * i0, o[dt][1] * i0);
        *reinterpret_cast<uint32_t*>(gy_h + (size_t)r1 * Cc + col) =
            packh(o[dt][2] * i1, o[dt][3] * i1);
    }
}

// ---------------------------------------------------------------------------
extern "C" void kernel_launch(void* const* d_in, const int* in_sizes, int n_in,
                              void* d_out, int out_size)
{
    (void)in_sizes; (void)n_in; (void)out_size;
    const float* x      = (const float*)d_in[0];
    const int*   pad    = (const int*)d_in[1];
    const float* w_attn = (const float*)d_in[2];
    const float* w_proj = (const float*)d_in[3];
    const float* b_proj = (const float*)d_in[4];
    float* out = (float*)d_out;

    cudaFuncSetAttribute(sa_gemm_mma<0>, cudaFuncAttributeMaxDynamicSharedMemorySize, GSM_BYTES);
    cudaFuncSetAttribute(sa_gemm_mma<1>, cudaFuncAttributeMaxDynamicSharedMemorySize, GSM_BYTES);
    cudaFuncSetAttribute(sa_attn_mma,    cudaFuncAttributeMaxDynamicSharedMemorySize, ASM_BYTES);

    void *pxh, *pyh, *pwah, *pwph;
    cudaGetSymbolAddress(&pxh, gx_h);
    cudaGetSymbolAddress(&pyh, gy_h);
    cudaGetSymbolAddress(&pwah, gwa_h);
    cudaGetSymbolAddress(&pwph, gwp_h);

    // Single fused conversion launch (x + both weight transposes)
    k_convert<<<XB + WAB + WPB, 256>>>((const float4*)x, w_attn, w_proj);

    sa_gemm_mma<0><<<dim3(3072 / 128, BT / 128), 256, GSM_BYTES>>>(
        (const __half*)pxh, (const __half*)pwah, nullptr, nullptr, 3072);

    sa_attn_mma<<<dim3(Tt / 128, Bb * Hh), 256, ASM_BYTES>>>(pad);

    sa_gemm_mma<1><<<dim3(1024 / 128, BT / 128), 256, GSM_BYTES>>>(
        (const __half*)pyh, (const __half*)pwph, b_proj, out, 1024);
}